// round 14
// baseline (speedup 1.0000x reference)
#include <cuda_runtime.h>
#include <cstdint>

// Problem constants (match reference)
#define B      32
#define TMAX   512
#define D      384
#define MAXDUR 8
#define TOUT   (TMAX * (MAXDUR - 1))   // 3584
#define VEC    (D / 4)                 // 96 float4 per row
#define CH     (D / 8)                 // 48 float8 (32B) chunks per row
#define ROWS_PER_CTA 8                 // 8 warps, 1 output row each
#define CTAS_PER_B   (TOUT / ROWS_PER_CTA)   // 448
#define NCTAS  (B * CTAS_PER_B)        // 14336

// 256-bit global load (non-coherent) — sm_100+ (PTX ISA 8.7)
__device__ __forceinline__ void ldg256(const float* __restrict__ p, float* r) {
    asm volatile(
        "ld.global.nc.v8.f32 {%0,%1,%2,%3,%4,%5,%6,%7}, [%8];"
        : "=f"(r[0]), "=f"(r[1]), "=f"(r[2]), "=f"(r[3]),
          "=f"(r[4]), "=f"(r[5]), "=f"(r[6]), "=f"(r[7])
        : "l"(p));
}

// 256-bit global store, evict-first (streaming) policy
__device__ __forceinline__ void stg256_cs(float* __restrict__ p, const float* r) {
    asm volatile(
        "st.global.cs.v8.f32 [%0], {%1,%2,%3,%4,%5,%6,%7,%8};"
        :: "l"(p),
           "f"(r[0]), "f"(r[1]), "f"(r[2]), "f"(r[3]),
           "f"(r[4]), "f"(r[5]), "f"(r[6]), "f"(r[7])
        : "memory");
}

// ---------------------------------------------------------------------------
// R4 structure (best measured 29.15us) with the gather/store path switched to
// 256-bit vector memory ops: halves L1tex wavefronts per byte (L1 was the
// highest mem metric, 57%, in every profile). Row = 48 x 32B chunks; each
// lane handles chunk `lane`, lanes 0-15 also handle chunk `lane+32`.
// ---------------------------------------------------------------------------
__global__ void __launch_bounds__(256) lenreg_fused_kernel(
    const float4* __restrict__ xs,     // [B, TMAX, VEC]
    const int*    __restrict__ ds,     // [B, TMAX]
    const int*    __restrict__ ilens,  // [B]
    float4*       __restrict__ out)    // [B, TOUT, VEC]
{
    const int cta    = blockIdx.x;
    const int b      = cta / CTAS_PER_B;              // mul-shift
    const int f_base = (cta - b * CTAS_PER_B) * ROWS_PER_CTA;

    const int t    = threadIdx.x;     // 0..255
    const int lane = t & 31;
    const int wid  = t >> 5;          // 0..7

    __shared__ int s_cum[TMAX];       // inclusive cumsum of masked durations
    __shared__ int s_wsum[8];

    const int L = ilens[b];

    // --- block scan: thread t owns elements 2t, 2t+1 --------------------
    const int e0 = 2 * t;
    const int e1 = 2 * t + 1;
    int d0 = (e0 < L) ? __ldg(ds + b * TMAX + e0) : 0;
    int d1 = (e1 < L) ? __ldg(ds + b * TMAX + e1) : 0;
    int pair = d0 + d1;

    // warp inclusive scan of pair sums
    int p = pair;
    #pragma unroll
    for (int off = 1; off < 32; off <<= 1) {
        int v = __shfl_up_sync(0xffffffffu, p, off);
        if (lane >= off) p += v;
    }
    if (lane == 31) s_wsum[wid] = p;
    __syncthreads();

    // cross-warp exclusive offset (8 values, scanned redundantly per thread)
    int woff = 0;
    #pragma unroll
    for (int w = 0; w < 8; ++w)
        woff += (w < wid) ? s_wsum[w] : 0;

    const int excl = p - pair + woff;     // exclusive prefix before e0
    s_cum[e0] = excl + d0;
    s_cum[e1] = excl + d0 + d1;
    __syncthreads();

    int total = s_cum[TMAX - 1];

    if (total == 0) {
        // all-zero fallback: d = mask -> cum[t'] = min(t'+1, L)
        s_cum[e0] = (e0 < L) ? (e0 + 1) : L;
        s_cum[e1] = (e1 < L) ? (e1 + 1) : L;
        total = L;                         // L >= 1 guaranteed
        __syncthreads();
    }

    // --- per-warp: binary search + gather --------------------------------
    const int f = f_base + wid;            // this warp's output frame

    // searchsorted(cum, f, side='right'): first idx with cum[idx] > f.
    // 10 iterations to fully collapse [0, 512] insertion range.
    int lo = 0, hi = TMAX;
    #pragma unroll
    for (int step = 0; step < 10; ++step) {
        int mid = (lo + hi) >> 1;
        if (s_cum[mid] <= f) lo = mid + 1; else hi = mid;
    }
    int idx = (lo < TMAX - 1) ? lo : (TMAX - 1);

    float* dstf = (float*)(out + ((long)b * TOUT + f) * VEC);

    if (f < total) {
        const float* srcf = (const float*)(xs + ((long)b * TMAX + idx) * VEC);
        float r0[8], r1[8];
        ldg256(srcf + lane * 8, r0);
        if (lane < CH - 32)                       // lanes 0..15
            ldg256(srcf + (lane + 32) * 8, r1);
        stg256_cs(dstf + lane * 8, r0);
        if (lane < CH - 32)
            stg256_cs(dstf + (lane + 32) * 8, r1);
    } else {
        float z[8] = {0.f, 0.f, 0.f, 0.f, 0.f, 0.f, 0.f, 0.f};
        stg256_cs(dstf + lane * 8, z);
        if (lane < CH - 32)
            stg256_cs(dstf + (lane + 32) * 8, z);
    }
}

extern "C" void kernel_launch(void* const* d_in, const int* in_sizes, int n_in,
                              void* d_out, int out_size)
{
    const float* xs    = (const float*)d_in[0];  // [B, TMAX, D] fp32
    const int*   ds    = (const int*)  d_in[1];  // [B, TMAX] int32
    const int*   ilens = (const int*)  d_in[2];  // [B] int32
    float*       out   = (float*)d_out;          // [B, TOUT, D] fp32

    lenreg_fused_kernel<<<NCTAS, 256>>>(
        (const float4*)xs, ds, ilens, (float4*)out);
}

// round 15
// speedup vs baseline: 1.1965x; 1.1965x over previous
#include <cuda_runtime.h>
#include <cstdint>

// Problem constants (match reference)
#define B      32
#define TMAX   512
#define D      384
#define MAXDUR 8
#define TOUT   (TMAX * (MAXDUR - 1))   // 3584
#define VEC    (D / 4)                 // 96 float4 per row
#define ROWS_PER_CTA 8                 // 8 warps, 1 output row each
#define CTAS_PER_B   (TOUT / ROWS_PER_CTA)   // 448
#define NCTAS  (B * CTAS_PER_B)        // 14336

// ---------------------------------------------------------------------------
// FINAL kernel — best measured configuration (29.15 / 29.38 / 29.44 / 29.47us
// over four independent runs). Single fused kernel, 256 thr = 8 warps/CTA:
//   1. loads its batch's 512 durations, masks by ilen, block-scans to smem cum
//   2. all-zero fallback (cum[t] = min(t+1, L))
//   3. each warp binary-searches its output frame f in cum (searchsorted right,
//      10 steps: insertion point range [0,512] needs ceil(log2(513)) = 10)
//   4. warp gathers 96 float4 of xs[b, idx, :] -> out row (streaming stores)
//
// Measured conclusions (R2-R14):
//   - HBM wall: 201 MB mandatory traffic @ ~6.9 TB/s effective (86% of spec).
//   - Issue/ALU utilization 9%-43% does not move the time (non-binding).
//   - CTA shape curve: 4/8 rows per CTA tie at the minimum; 16/32 regress.
//   - __stcs beats __stwt (+5.3us), smem + cp.async.bulk (+5.9us), and
//     256-bit v8 ld/st (+5.5us; v8 cracks to 2 wavefronts in L1, no gain).
// ---------------------------------------------------------------------------
__global__ void __launch_bounds__(256) lenreg_fused_kernel(
    const float4* __restrict__ xs,     // [B, TMAX, VEC]
    const int*    __restrict__ ds,     // [B, TMAX]
    const int*    __restrict__ ilens,  // [B]
    float4*       __restrict__ out)    // [B, TOUT, VEC]
{
    const int cta    = blockIdx.x;
    const int b      = cta / CTAS_PER_B;              // mul-shift
    const int f_base = (cta - b * CTAS_PER_B) * ROWS_PER_CTA;

    const int t    = threadIdx.x;     // 0..255
    const int lane = t & 31;
    const int wid  = t >> 5;          // 0..7

    __shared__ int s_cum[TMAX];       // inclusive cumsum of masked durations
    __shared__ int s_wsum[8];

    const int L = ilens[b];

    // --- block scan: thread t owns elements 2t, 2t+1 --------------------
    const int e0 = 2 * t;
    const int e1 = 2 * t + 1;
    int d0 = (e0 < L) ? __ldg(ds + b * TMAX + e0) : 0;
    int d1 = (e1 < L) ? __ldg(ds + b * TMAX + e1) : 0;
    int pair = d0 + d1;

    // warp inclusive scan of pair sums
    int p = pair;
    #pragma unroll
    for (int off = 1; off < 32; off <<= 1) {
        int v = __shfl_up_sync(0xffffffffu, p, off);
        if (lane >= off) p += v;
    }
    if (lane == 31) s_wsum[wid] = p;
    __syncthreads();

    // cross-warp exclusive offset (8 values, scanned redundantly per thread)
    int woff = 0;
    #pragma unroll
    for (int w = 0; w < 8; ++w)
        woff += (w < wid) ? s_wsum[w] : 0;

    const int excl = p - pair + woff;     // exclusive prefix before e0
    s_cum[e0] = excl + d0;
    s_cum[e1] = excl + d0 + d1;
    __syncthreads();

    int total = s_cum[TMAX - 1];

    if (total == 0) {
        // all-zero fallback: d = mask -> cum[t'] = min(t'+1, L)
        s_cum[e0] = (e0 < L) ? (e0 + 1) : L;
        s_cum[e1] = (e1 < L) ? (e1 + 1) : L;
        total = L;                         // L >= 1 guaranteed
        __syncthreads();
    }

    // --- per-warp: binary search + gather --------------------------------
    const int f = f_base + wid;            // this warp's output frame

    // searchsorted(cum, f, side='right'): first idx with cum[idx] > f.
    // 10 iterations to fully collapse [0, 512] insertion range.
    int lo = 0, hi = TMAX;
    #pragma unroll
    for (int step = 0; step < 10; ++step) {
        int mid = (lo + hi) >> 1;
        if (s_cum[mid] <= f) lo = mid + 1; else hi = mid;
    }
    int idx = (lo < TMAX - 1) ? lo : (TMAX - 1);

    float4* dst = out + ((long)b * TOUT + f) * VEC;

    if (f < total) {
        const float4* src = xs + ((long)b * TMAX + idx) * VEC;
        float4 r0 = __ldg(src + lane);
        float4 r1 = __ldg(src + lane + 32);
        float4 r2 = __ldg(src + lane + 64);
        __stcs(dst + lane,      r0);
        __stcs(dst + lane + 32, r1);
        __stcs(dst + lane + 64, r2);
    } else {
        const float4 z = make_float4(0.f, 0.f, 0.f, 0.f);
        __stcs(dst + lane,      z);
        __stcs(dst + lane + 32, z);
        __stcs(dst + lane + 64, z);
    }
}

extern "C" void kernel_launch(void* const* d_in, const int* in_sizes, int n_in,
                              void* d_out, int out_size)
{
    const float* xs    = (const float*)d_in[0];  // [B, TMAX, D] fp32
    const int*   ds    = (const int*)  d_in[1];  // [B, TMAX] int32
    const int*   ilens = (const int*)  d_in[2];  // [B] int32
    float*       out   = (float*)d_out;          // [B, TOUT, D] fp32

    lenreg_fused_kernel<<<NCTAS, 256>>>(
        (const float4*)xs, ds, ilens, (float4*)out);
}